// round 3
// baseline (speedup 1.0000x reference)
#include <cuda_runtime.h>
#include <cstdint>

// PositionDropout fused: out[b,s,d] = scale[b,s] * x[b,s,d]
// One kernel. Each block owns 8 consecutive (b,s) rows:
//   - threads 0..7 compute scale[row] (Threefry-2x32 bernoulli + prox) -> smem
//   - all 192 threads stream 8 rows: 8 front-batched float4 loads (MLP=8),
//     streaming cache hints (read-once / write-once).

#define B_  64
#define S_  512
#define D_  768
#define NROWS (B_ * S_)        // 32768
#define V4_PER_ROW (D_ / 4)    // 192
#define RPB 8                  // rows per block
#define NBLK (NROWS / RPB)     // 4096

// Threefry-2x32, 20 rounds, key (0, 42). ks2 = k1 ^ k2 ^ 0x1BD11BDA.
__device__ __forceinline__ uint32_t threefry_bits_0_42(uint32_t i) {
    const uint32_t ks0 = 0u;
    const uint32_t ks1 = 42u;
    const uint32_t ks2 = 0x1BD11BDAu ^ 0u ^ 42u;
    uint32_t x0 = 0u + ks0;    // counter hi = 0
    uint32_t x1 = i + ks1;     // counter lo = linear index
#define TF_R(r) { x0 += x1; x1 = __funnelshift_l(x1, x1, (r)); x1 ^= x0; }
    TF_R(13) TF_R(15) TF_R(26) TF_R(6)   x0 += ks1; x1 += ks2 + 1u;
    TF_R(17) TF_R(29) TF_R(16) TF_R(24)  x0 += ks2; x1 += ks0 + 2u;
    TF_R(13) TF_R(15) TF_R(26) TF_R(6)   x0 += ks0; x1 += ks1 + 3u;
    TF_R(17) TF_R(29) TF_R(16) TF_R(24)  x0 += ks1; x1 += ks2 + 4u;
    TF_R(13) TF_R(15) TF_R(26) TF_R(6)   x0 += ks2; x1 += ks0 + 5u;
#undef TF_R
    return x0 ^ x1;
}

__global__ void __launch_bounds__(V4_PER_ROW) pd_fused_kernel(
        const float4* __restrict__ x,
        float4* __restrict__ out,
        const int* __restrict__ abi,   // [B,2]
        const int* __restrict__ tl,    // [B]
        const int* __restrict__ al) {  // [B]
    __shared__ float s_sc[RPB];

    unsigned row0 = blockIdx.x * RPB;
    unsigned t = threadIdx.x;

    if (t < RPB) {
        unsigned i = row0 + t;                 // linear [B,S] index
        uint32_t bits = threefry_bits_0_42(i);
        // uniform in [0,1): bitcast((bits>>9) | 0x3f800000) - 1.0f
        float u = __uint_as_float((bits >> 9) | 0x3F800000u) - 1.0f;

        int b = i >> 9;                        // i / S_
        int s = i & (S_ - 1);

        int b0i = abi[2 * b];
        int b1i = abi[2 * b + 1];
        int tli = tl[b];
        int ctxi = tli - al[b];

        float jf  = (float)s;
        float b0f = (float)b0i;
        float b1f = (float)b1i;
        float ctx = (float)ctxi;

        float prox;
        if (jf < b0f)        prox = 1.0f - __fdiv_rn(b0f - jf, ctx);
        else if (jf <= b1f)  prox = __fdiv_rn(1.0f, ctx);
        else                 prox = 1.0f - __fdiv_rn(jf - b1f, ctx);
        if (!(jf < (float)tli)) prox = 0.0f;
        prox = fminf(fmaxf(prox, 0.0f), 1.0f);

        float mask = (u < prox) ? 1.0f : 0.0f;
        s_sc[t] = __fdiv_rn(mask, prox + 1e-5f);
    }
    __syncthreads();

    // Stream 8 rows, front-batched streaming loads for MLP=8.
    const float4* xp = x + (size_t)row0 * V4_PER_ROW + t;
    float4 v[RPB];
#pragma unroll
    for (int r = 0; r < RPB; r++)
        v[r] = __ldcs(xp + r * V4_PER_ROW);

    float sc[RPB];
#pragma unroll
    for (int r = 0; r < RPB; r++) sc[r] = s_sc[r];

#pragma unroll
    for (int r = 0; r < RPB; r++) {
        v[r].x *= sc[r]; v[r].y *= sc[r];
        v[r].z *= sc[r]; v[r].w *= sc[r];
    }

    float4* op = out + (size_t)row0 * V4_PER_ROW + t;
#pragma unroll
    for (int r = 0; r < RPB; r++)
        __stcs(op + r * V4_PER_ROW, v[r]);
}

extern "C" void kernel_launch(void* const* d_in, const int* in_sizes, int n_in,
                              void* d_out, int out_size) {
    const float* x   = (const float*)d_in[0];
    const int*   abi = (const int*)d_in[1];
    const int*   tl  = (const int*)d_in[2];
    const int*   al  = (const int*)d_in[3];
    float* out = (float*)d_out;

    pd_fused_kernel<<<NBLK, V4_PER_ROW>>>((const float4*)x, (float4*)out,
                                          abi, tl, al);
}